// round 11
// baseline (speedup 1.0000x reference)
#include <cuda_runtime.h>
#include <cuda_bf16.h>
#include <math.h>

// PositionCollapseLoss, single kernel, fence-free deterministic finalize.
//
// Per-block 9 fp32 moments -> i64 fixed-point (x 2^32, exact via double) ->
// relaxed atomicAdd into per-batch accumulators (integer: associative =>
// bitwise deterministic). acq_rel ticket per batch; 32nd arrival computes the
// batch eigen/log, adds fixed-point log into a global accumulator; 32nd batch
// winner writes the output and resets globals for the next graph replay.
// No __threadfence / MEMBAR anywhere (R7 showed per-block gpu fences cost ~4us).

#define B_DIM   32
#define N_PTS   65536
#define N_CH    14
#define CHUNKS  32          // blocks per batch
#define THREADS 256
#define PTS_PER_BLK (N_PTS / CHUNKS)   // 2048
#define GRID    (B_DIM * CHUNKS)       // 1024

#define FX_SCALE 4294967296.0          // 2^32

__device__ unsigned long long g_sums[B_DIM][9]; // zero-init (static storage)
__device__ unsigned int       g_bcnt[B_DIM];
__device__ unsigned long long g_loss;
__device__ unsigned int       g_done;

__device__ __forceinline__ unsigned int atom_inc_acq_rel(unsigned int* p) {
    unsigned int old;
    asm volatile("atom.add.acq_rel.gpu.u32 %0, [%1], 1;"
                 : "=r"(old) : "l"(p) : "memory");
    return old;
}

__device__ __forceinline__ long long ld_acq_s64(const unsigned long long* p) {
    long long v;
    asm volatile("ld.acquire.gpu.b64 %0, [%1];" : "=l"(v) : "l"(p) : "memory");
    return v;
}

__device__ __forceinline__ long long to_fx(float v) {
    return __double2ll_rn((double)v * FX_SCALE);   // exact product in double
}

__device__ __forceinline__ float sanitize_f(float x) {
    if (isnan(x)) x = 0.0f;
    if (x >  1.0e6f) x =  1.0e6f;
    if (x < -1.0e6f) x = -1.0e6f;
    return x;
}

// Analytic eigen range of symmetric 3x3 from raw moment sums, then log(clip).
__device__ __forceinline__ float batch_log_ratio(const float* s) {
    const float invN = 1.0f / (float)N_PTS;
    const float mx = s[0] * invN, my = s[1] * invN, mz = s[2] * invN;
    float cxx = sanitize_f(s[3] * invN - mx * mx);
    float cxy = sanitize_f(s[4] * invN - mx * my);
    float cxz = sanitize_f(s[5] * invN - mx * mz);
    float cyy = sanitize_f(s[6] * invN - my * my);
    float cyz = sanitize_f(s[7] * invN - my * mz);
    float czz = sanitize_f(s[8] * invN - mz * mz);

    const float q  = (cxx + cyy + czz) * (1.0f / 3.0f);
    const float p1 = cxy * cxy + cxz * cxz + cyz * cyz;
    const float d1 = cxx - q, d2 = cyy - q, d3 = czz - q;
    const float p2 = d1 * d1 + d2 * d2 + d3 * d3 + 2.0f * p1;

    float emax, emin;
    if (p2 <= 0.0f) {
        emax = q; emin = q;
    } else {
        const float p  = sqrtf(p2 * (1.0f / 6.0f));
        const float ip = 1.0f / p;
        const float b11 = d1 * ip, b22 = d2 * ip, b33 = d3 * ip;
        const float b12 = cxy * ip, b13 = cxz * ip, b23 = cyz * ip;
        float detB = b11 * (b22 * b33 - b23 * b23)
                   - b12 * (b12 * b33 - b23 * b13)
                   + b13 * (b12 * b23 - b22 * b13);
        float r = detB * 0.5f;
        r = fminf(1.0f, fmaxf(-1.0f, r));
        const float phi = acosf(r) * (1.0f / 3.0f);
        emax = q + 2.0f * p * cosf(phi);
        emin = q + 2.0f * p * cosf(phi + 2.0943951023931953f); // +2pi/3
    }

    emax = fmaxf(sanitize_f(emax), 1e-6f);
    emin = fmaxf(sanitize_f(emin), 1e-6f);
    float ratio = emax / emin;
    ratio = fminf(1.0e6f, fmaxf(1.0f, ratio));
    return logf(ratio);
}

__global__ __launch_bounds__(THREADS)
void pcl_kernel(const float* __restrict__ g, float* __restrict__ out) {
    const int blk = blockIdx.x;                 // 0 .. GRID-1
    const int b   = blk / CHUNKS;
    const int c   = blk % CHUNKS;
    const int n0  = c * PTS_PER_BLK;

    const float* __restrict__ base = g + (size_t)b * (N_PTS * N_CH);

    float sx = 0.f, sy = 0.f, sz = 0.f;
    float sxx = 0.f, sxy = 0.f, sxz = 0.f;
    float syy = 0.f, syz = 0.f, szz = 0.f;

    #pragma unroll
    for (int it = 0; it < PTS_PER_BLK / THREADS; ++it) {
        const int i = n0 + it * THREADS + threadIdx.x;
        const int off = i * N_CH;               // < 13M, fits int
        // 56-byte point stride => always 8-byte aligned: float2 + scalar
        const float2 xy = *reinterpret_cast<const float2*>(base + off);
        const float  z  = base[off + 2];
        const float x = xy.x, y = xy.y;
        sx += x;  sy += y;  sz += z;
        sxx += x * x;  sxy += x * y;  sxz += x * z;
        syy += y * y;  syz += y * z;  szz += z * z;
    }

    float s[9] = {sx, sy, sz, sxx, sxy, sxz, syy, syz, szz};

    #pragma unroll
    for (int k = 0; k < 9; ++k) {
        #pragma unroll
        for (int m = 16; m > 0; m >>= 1)
            s[k] += __shfl_xor_sync(0xffffffffu, s[k], m);
    }

    __shared__ float sm[THREADS / 32][9];
    const int warp = threadIdx.x >> 5;
    const int lane = threadIdx.x & 31;
    if (lane == 0) {
        #pragma unroll
        for (int k = 0; k < 9; ++k) sm[warp][k] = s[k];
    }
    __syncthreads();

    if (warp != 0) return;

    // second-stage reduce; lane 0 publishes each sum via relaxed i64 atomicAdd
    #pragma unroll
    for (int k = 0; k < 9; ++k) {
        float v = (lane < (THREADS / 32)) ? sm[lane][k] : 0.f;
        #pragma unroll
        for (int m = 4; m > 0; m >>= 1)
            v += __shfl_xor_sync(0xffffffffu, v, m);
        if (lane == 0)
            atomicAdd(&g_sums[b][k], (unsigned long long)to_fx(v));
    }

    if (lane != 0) return;

    // per-batch ticket: release orders the 9 atomics above; acquire lets the
    // winner see everyone's contributions.
    const unsigned int old = atom_inc_acq_rel(&g_bcnt[b]);
    if (old != CHUNKS - 1) return;

    // ---- batch winner: finalize batch b ----
    float fs[9];
    #pragma unroll
    for (int k = 0; k < 9; ++k)
        fs[k] = (float)((double)ld_acq_s64(&g_sums[b][k]) * (1.0 / FX_SCALE));

    // reset own batch state for the next graph replay (no other block touches
    // batch b anymore; ordered before g_done release below)
    #pragma unroll
    for (int k = 0; k < 9; ++k) g_sums[b][k] = 0ull;
    g_bcnt[b] = 0u;

    const float lr = batch_log_ratio(fs);
    atomicAdd(&g_loss, (unsigned long long)__double2ll_rn((double)lr * FX_SCALE));

    const unsigned int d = atom_inc_acq_rel(&g_done);
    if (d != B_DIM - 1) return;

    // ---- final winner: write output, reset globals ----
    const long long acc = ld_acq_s64(&g_loss);
    out[0] = (float)(-(double)acc / FX_SCALE / (double)B_DIM);
    g_loss = 0ull;
    g_done = 0u;
}

extern "C" void kernel_launch(void* const* d_in, const int* in_sizes, int n_in,
                              void* d_out, int out_size) {
    (void)in_sizes; (void)n_in; (void)out_size;
    const float* g = (const float*)d_in[0];
    float* out = (float*)d_out;
    pcl_kernel<<<GRID, THREADS>>>(g, out);
}

// round 12
// speedup vs baseline: 1.3582x; 1.3582x over previous
#include <cuda_runtime.h>
#include <cuda_bf16.h>
#include <math.h>

// PositionCollapseLoss, single kernel + dedicated spinner block.
//
// Blocks 1..1024: 9 fp32 moments for (batch, chunk); publish as i64 fixed-
//   point via fire-and-forget red.relaxed (no return wait), then one
//   red.release ticket bump. No fences, no winner work, no ATOMG waits.
// Block 0 (spinner warp): lane b polls g_bcnt[b] with ld.acquire; when its
//   batch's 32 chunks have arrived it loads the 9 sums, computes the 3x3
//   eigen ratio log (32 lanes in parallel), shfl-reduces, writes out, and
//   resets all globals for the next graph replay.

#define B_DIM   32
#define N_PTS   65536
#define N_CH    14
#define CHUNKS  32
#define THREADS 256
#define PTS_PER_BLK (N_PTS / CHUNKS)   // 2048
#define GRID    (B_DIM * CHUNKS + 1)   // 1025 (block 0 = spinner)

#define FX_SCALE 4294967296.0          // 2^32

__device__ unsigned long long g_sums[B_DIM][9];  // zero-init static storage
__device__ unsigned int       g_bcnt[B_DIM];

__device__ __forceinline__ void red_add_relaxed_u64(unsigned long long* p,
                                                    unsigned long long v) {
    asm volatile("red.relaxed.gpu.global.add.u64 [%0], %1;"
                 :: "l"(p), "l"(v) : "memory");
}

__device__ __forceinline__ void red_add_release_u32(unsigned int* p) {
    asm volatile("red.release.gpu.global.add.u32 [%0], 1;"
                 :: "l"(p) : "memory");
}

__device__ __forceinline__ unsigned int ld_acq_u32(const unsigned int* p) {
    unsigned int v;
    asm volatile("ld.acquire.gpu.global.u32 %0, [%1];"
                 : "=r"(v) : "l"(p) : "memory");
    return v;
}

__device__ __forceinline__ unsigned long long ld_rlx_u64(const unsigned long long* p) {
    unsigned long long v;
    asm volatile("ld.relaxed.gpu.global.u64 %0, [%1];"
                 : "=l"(v) : "l"(p) : "memory");
    return v;
}

__device__ __forceinline__ float sanitize_f(float x) {
    if (isnan(x)) x = 0.0f;
    if (x >  1.0e6f) x =  1.0e6f;
    if (x < -1.0e6f) x = -1.0e6f;
    return x;
}

// Analytic eigen range of symmetric 3x3 from raw moment sums, then log(clip).
__device__ __forceinline__ float batch_log_ratio(const float* s) {
    const float invN = 1.0f / (float)N_PTS;
    const float mx = s[0] * invN, my = s[1] * invN, mz = s[2] * invN;
    float cxx = sanitize_f(s[3] * invN - mx * mx);
    float cxy = sanitize_f(s[4] * invN - mx * my);
    float cxz = sanitize_f(s[5] * invN - mx * mz);
    float cyy = sanitize_f(s[6] * invN - my * my);
    float cyz = sanitize_f(s[7] * invN - my * mz);
    float czz = sanitize_f(s[8] * invN - mz * mz);

    const float q  = (cxx + cyy + czz) * (1.0f / 3.0f);
    const float p1 = cxy * cxy + cxz * cxz + cyz * cyz;
    const float d1 = cxx - q, d2 = cyy - q, d3 = czz - q;
    const float p2 = d1 * d1 + d2 * d2 + d3 * d3 + 2.0f * p1;

    float emax, emin;
    if (p2 <= 0.0f) {
        emax = q; emin = q;
    } else {
        const float p  = sqrtf(p2 * (1.0f / 6.0f));
        const float ip = 1.0f / p;
        const float b11 = d1 * ip, b22 = d2 * ip, b33 = d3 * ip;
        const float b12 = cxy * ip, b13 = cxz * ip, b23 = cyz * ip;
        float detB = b11 * (b22 * b33 - b23 * b23)
                   - b12 * (b12 * b33 - b23 * b13)
                   + b13 * (b12 * b23 - b22 * b13);
        float r = detB * 0.5f;
        r = fminf(1.0f, fmaxf(-1.0f, r));
        const float phi = acosf(r) * (1.0f / 3.0f);
        emax = q + 2.0f * p * cosf(phi);
        emin = q + 2.0f * p * cosf(phi + 2.0943951023931953f); // +2pi/3
    }

    emax = fmaxf(sanitize_f(emax), 1e-6f);
    emin = fmaxf(sanitize_f(emin), 1e-6f);
    float ratio = emax / emin;
    ratio = fminf(1.0e6f, fmaxf(1.0f, ratio));
    return logf(ratio);
}

__global__ __launch_bounds__(THREADS)
void pcl_kernel(const float* __restrict__ g, float* __restrict__ out) {
    // ---------------- spinner block ----------------
    if (blockIdx.x == 0) {
        if (threadIdx.x >= 32) return;
        const int b = threadIdx.x;    // lane = batch

        // poll my batch ticket until all CHUNKS producers released
        bool done = false;
        while (!__all_sync(0xffffffffu, done)) {
            if (!done) done = (ld_acq_u32(&g_bcnt[b]) >= CHUNKS);
            if (!__all_sync(0xffffffffu, done)) __nanosleep(64);
        }

        float fs[9];
        #pragma unroll
        for (int k = 0; k < 9; ++k)
            fs[k] = (float)((double)(long long)ld_rlx_u64(&g_sums[b][k])
                            * (1.0 / FX_SCALE));

        // reset for next graph replay (kernel-completion orders vs next launch)
        #pragma unroll
        for (int k = 0; k < 9; ++k) g_sums[b][k] = 0ull;
        g_bcnt[b] = 0u;

        float l = batch_log_ratio(fs);   // 32 batches in parallel, one per lane
        #pragma unroll
        for (int m = 16; m > 0; m >>= 1)
            l += __shfl_xor_sync(0xffffffffu, l, m);
        if (b == 0) out[0] = -l * (1.0f / (float)B_DIM);
        return;
    }

    // ---------------- producer blocks ----------------
    const int blk = blockIdx.x - 1;             // 0 .. 1023
    const int b   = blk / CHUNKS;
    const int c   = blk % CHUNKS;
    const int n0  = c * PTS_PER_BLK;

    const float* __restrict__ base = g + (size_t)b * (N_PTS * N_CH);

    float sx = 0.f, sy = 0.f, sz = 0.f;
    float sxx = 0.f, sxy = 0.f, sxz = 0.f;
    float syy = 0.f, syz = 0.f, szz = 0.f;

    #pragma unroll
    for (int it = 0; it < PTS_PER_BLK / THREADS; ++it) {
        const int i = n0 + it * THREADS + threadIdx.x;
        const int off = i * N_CH;               // < 1M, fits int
        // 56-byte point stride => always 8-byte aligned: float2 + scalar
        const float2 xy = *reinterpret_cast<const float2*>(base + off);
        const float  z  = base[off + 2];
        const float x = xy.x, y = xy.y;
        sx += x;  sy += y;  sz += z;
        sxx += x * x;  sxy += x * y;  sxz += x * z;
        syy += y * y;  syz += y * z;  szz += z * z;
    }

    float s[9] = {sx, sy, sz, sxx, sxy, sxz, syy, syz, szz};

    #pragma unroll
    for (int k = 0; k < 9; ++k) {
        #pragma unroll
        for (int m = 16; m > 0; m >>= 1)
            s[k] += __shfl_xor_sync(0xffffffffu, s[k], m);
    }

    __shared__ float sm[THREADS / 32][9];
    const int warp = threadIdx.x >> 5;
    const int lane = threadIdx.x & 31;
    if (lane == 0) {
        #pragma unroll
        for (int k = 0; k < 9; ++k) sm[warp][k] = s[k];
    }
    __syncthreads();

    if (warp != 0) return;

    #pragma unroll
    for (int k = 0; k < 9; ++k) {
        float v = (lane < (THREADS / 32)) ? sm[lane][k] : 0.f;
        #pragma unroll
        for (int m = 4; m > 0; m >>= 1)
            v += __shfl_xor_sync(0xffffffffu, v, m);
        if (lane == 0) {
            // exact fixed-point conversion (double product), fire-and-forget
            red_add_relaxed_u64(&g_sums[b][k],
                (unsigned long long)__double2ll_rn((double)v * FX_SCALE));
        }
    }

    if (lane == 0) red_add_release_u32(&g_bcnt[b]);  // orders the 9 REDs
}

extern "C" void kernel_launch(void* const* d_in, const int* in_sizes, int n_in,
                              void* d_out, int out_size) {
    (void)in_sizes; (void)n_in; (void)out_size;
    const float* g = (const float*)d_in[0];
    float* out = (float*)d_out;
    pcl_kernel<<<GRID, THREADS>>>(g, out);
}